// round 10
// baseline (speedup 1.0000x reference)
#include <cuda_runtime.h>
#include <cstdint>

// Shapes (fixed by the problem)
#define BB 64
#define NN 21
#define HH 128
#define WW 128
// Total float4 = 5,505,024 = 512 * 10,752 (exact)

static constexpr int GRID    = 592;    // 148 SMs * 4
static constexpr int THREADS = 256;
static constexpr int TILE    = 512;    // float4 per array per stage (8KB)
static constexpr int NTILES  = 5505024 / TILE;   // 10752
static constexpr int DEPTH   = 2;
static constexpr int NKP     = BB * NN;          // 1344 keypoints
static constexpr unsigned STAGE_BYTES = TILE * 16 * 2;  // 16384 (both arrays)

__device__ float2 g_part[GRID];
__device__ unsigned int g_done_ctr;

__device__ __forceinline__ float warp_sum(float v) {
    #pragma unroll
    for (int off = 16; off > 0; off >>= 1)
        v += __shfl_down_sync(0xFFFFFFFFu, v, off);
    return v;
}

__device__ __forceinline__ float sqdiff4(float4 a, float4 b, float acc) {
    float d;
    d = a.x - b.x; acc = fmaf(d, d, acc);
    d = a.y - b.y; acc = fmaf(d, d, acc);
    d = a.z - b.z; acc = fmaf(d, d, acc);
    d = a.w - b.w; acc = fmaf(d, d, acc);
    return acc;
}

__device__ __forceinline__ uint32_t smem_u32(const void* p) {
    return (uint32_t)__cvta_generic_to_shared(p);
}

__device__ __forceinline__ void mbar_init(uint32_t mbar, uint32_t count) {
    asm volatile("mbarrier.init.shared.b64 [%0], %1;" :: "r"(mbar), "r"(count) : "memory");
}
__device__ __forceinline__ void mbar_expect_tx(uint32_t mbar, uint32_t bytes) {
    asm volatile("mbarrier.arrive.expect_tx.shared.b64 _, [%0], %1;" :: "r"(mbar), "r"(bytes) : "memory");
}
__device__ __forceinline__ void mbar_arrive(uint32_t mbar) {
    asm volatile("mbarrier.arrive.shared.b64 _, [%0];" :: "r"(mbar) : "memory");
}
__device__ __forceinline__ void mbar_wait(uint32_t mbar, uint32_t parity) {
    asm volatile(
        "{\n\t"
        ".reg .pred P;\n\t"
        "WAIT_%=:\n\t"
        "mbarrier.try_wait.parity.acquire.cta.shared::cta.b64 P, [%0], %1, 0x989680;\n\t"
        "@P bra.uni DONE_%=;\n\t"
        "bra.uni WAIT_%=;\n\t"
        "DONE_%=:\n\t"
        "}"
        :: "r"(mbar), "r"(parity) : "memory");
}
__device__ __forceinline__ void mbar_wait_relaxed(uint32_t mbar, uint32_t parity) {
    asm volatile(
        "{\n\t"
        ".reg .pred P;\n\t"
        "WAIT_%=:\n\t"
        "mbarrier.try_wait.parity.relaxed.cta.shared::cta.b64 P, [%0], %1, 0x989680;\n\t"
        "@P bra.uni DONE_%=;\n\t"
        "bra.uni WAIT_%=;\n\t"
        "DONE_%=:\n\t"
        "}"
        :: "r"(mbar), "r"(parity) : "memory");
}
// 1D bulk copy GMEM -> SMEM, completion via mbarrier complete_tx
__device__ __forceinline__ void bulk_g2s(uint32_t dst, const void* src, uint32_t bytes, uint32_t mbar) {
    asm volatile(
        "cp.async.bulk.shared::cluster.global.mbarrier::complete_tx::bytes [%0], [%1], %2, [%3];"
        :: "r"(dst), "l"(src), "r"(bytes), "r"(mbar) : "memory");
}

__global__ void __launch_bounds__(THREADS, 4) fused_loss_kernel(
    const float4* __restrict__ pred4,
    const float4* __restrict__ gt4,
    const float*  __restrict__ pred,
    const float*  __restrict__ kp,
    float* __restrict__ out)
{
    __shared__ __align__(16) float4 bufA[DEPTH][TILE];
    __shared__ __align__(16) float4 bufB[DEPTH][TILE];
    __shared__ __align__(8) unsigned long long mbar_store[2 * DEPTH];

    const int tid = threadIdx.x;
    const int b   = blockIdx.x;
    const uint32_t mb = smem_u32(mbar_store);
    auto full_bar  = [&](int s) { return mb + s * 8; };
    auto empty_bar = [&](int s) { return mb + (DEPTH + s) * 8; };

    if (tid == 0) {
        #pragma unroll
        for (int s = 0; s < DEPTH; s++) {
            mbar_init(full_bar(s), 1);
            mbar_init(empty_bar(s), THREADS);
        }
    }
    __syncthreads();

    // Tiles for this CTA: b, b+GRID, ...  (NTILES = 10752, GRID = 592 -> 18 or 19)
    const int nt = (NTILES - b + GRID - 1) / GRID;

    // Prologue: issue first DEPTH stages
    if (tid == 0) {
        #pragma unroll
        for (int k = 0; k < DEPTH; k++) {
            if (k < nt) {
                const int tile = b + k * GRID;
                mbar_expect_tx(full_bar(k), STAGE_BYTES);
                bulk_g2s(smem_u32(bufA[k]), pred4 + (size_t)tile * TILE, TILE * 16, full_bar(k));
                bulk_g2s(smem_u32(bufB[k]), gt4   + (size_t)tile * TILE, TILE * 16, full_bar(k));
            }
        }
    }

    // ---- keypoint gather (overlaps with first stage arrival) ----
    const int tid_global = b * THREADS + tid;
    float pck_acc = 0.0f;
    if (tid_global < NKP) {
        float2 xy = *(const float2*)&kp[2 * tid_global];
        int x = (int)fminf(fmaxf(xy.x, 0.0f), (float)(WW - 1));
        int y = (int)fminf(fmaxf(xy.y, 0.0f), (float)(HH - 1));
        float v = pred[(tid_global * HH + y) * WW + x];
        float e = 1.0f - v;
        pck_acc = e * e;
    }

    // ---- pipelined consume ----
    float acc0 = 0.0f, acc1 = 0.0f;
    #pragma unroll 1
    for (int k = 0; k < nt; k++) {
        const int s  = k & 1;
        const uint32_t ph = (k >> 1) & 1;
        mbar_wait(full_bar(s), ph);

        float4 a0 = bufA[s][tid];
        float4 a1 = bufA[s][tid + THREADS];
        float4 b0 = bufB[s][tid];
        float4 b1 = bufB[s][tid + THREADS];
        acc0 = sqdiff4(a0, b0, acc0);
        acc1 = sqdiff4(a1, b1, acc1);

        mbar_arrive(empty_bar(s));

        if (tid == 0 && k + DEPTH < nt) {
            const int kk = k + DEPTH;
            const int ss = kk & 1;
            // wait until all 256 consumers released this buffer
            mbar_wait_relaxed(empty_bar(ss), ((kk >> 1) - 1) & 1);
            const int tile = b + kk * GRID;
            mbar_expect_tx(full_bar(ss), STAGE_BYTES);
            bulk_g2s(smem_u32(bufA[ss]), pred4 + (size_t)tile * TILE, TILE * 16, full_bar(ss));
            bulk_g2s(smem_u32(bufB[ss]), gt4   + (size_t)tile * TILE, TILE * 16, full_bar(ss));
        }
    }
    float mse_acc = acc0 + acc1;

    // ---- block reduction ----
    __shared__ float s1[THREADS / 32];
    __shared__ float s2[THREADS / 32];
    int lane = tid & 31;
    int wid  = tid >> 5;
    float m = warp_sum(mse_acc);
    float p = warp_sum(pck_acc);
    if (lane == 0) { s1[wid] = m; s2[wid] = p; }
    __syncthreads();

    __shared__ bool s_is_last;
    if (wid == 0) {
        float mm = (lane < THREADS / 32) ? s1[lane] : 0.0f;
        float pp = (lane < THREADS / 32) ? s2[lane] : 0.0f;
        mm = warp_sum(mm);
        pp = warp_sum(pp);
        if (lane == 0) {
            g_part[b] = make_float2(mm, pp);
            __threadfence();
            unsigned int prev = atomicAdd(&g_done_ctr, 1u);
            s_is_last = (prev == (unsigned int)(gridDim.x - 1));
        }
    }
    __syncthreads();

    // ---- last block finalizes ----
    if (s_is_last) {
        float ma = 0.0f, pa = 0.0f;
        for (int j = tid; j < GRID; j += THREADS) {
            float2 v = g_part[j];
            ma += v.x;
            pa += v.y;
        }
        float mw = warp_sum(ma);
        float pw = warp_sum(pa);
        if (lane == 0) { s1[wid] = mw; s2[wid] = pw; }
        __syncthreads();
        if (wid == 0) {
            float mm = (lane < THREADS / 32) ? s1[lane] : 0.0f;
            float pp = (lane < THREADS / 32) ? s2[lane] : 0.0f;
            mm = warp_sum(mm);
            pp = warp_sum(pp);
            if (lane == 0) {
                float mse = mm / (float)((long long)BB * NN * HH * WW);
                float pck = pp / (float)NKP;
                out[0] = mse + pck;
                out[1] = mse;
                out[2] = pck;
                g_done_ctr = 0;
            }
        }
    }
}

extern "C" void kernel_launch(void* const* d_in, const int* in_sizes, int n_in,
                              void* d_out, int out_size)
{
    const float* pred = (const float*)d_in[0];
    const float* gt   = (const float*)d_in[1];
    const float* kp   = (const float*)d_in[2];
    float* out = (float*)d_out;

    fused_loss_kernel<<<GRID, THREADS>>>(
        (const float4*)pred, (const float4*)gt, pred, kp, out);
}

// round 11
// speedup vs baseline: 1.0138x; 1.0138x over previous
#include <cuda_runtime.h>

// Shapes (fixed by the problem)
#define BB 64
#define NN 21
#define HH 128
#define WW 128
// Total float4 = 5,505,024 = 21 * 2^18 = 4096 warps * 7 chunks * 192 float4 (EXACT)

static constexpr int GRID    = 512;    // 4096 warps total
static constexpr int THREADS = 256;
static constexpr int UNROLL  = 6;
static constexpr int CHUNK   = 32 * UNROLL;              // 192 float4 (3KB) per warp-chunk
static constexpr int TOTAL_WARPS = GRID * (THREADS / 32); // 4096
static constexpr int CHUNKS_PER_WARP = 5505024 / CHUNK / TOTAL_WARPS; // exactly 7
static constexpr int NKP = BB * NN;    // 1344 keypoints

__device__ float2 g_part[GRID];        // (mse, pck) partials
__device__ unsigned int g_done_ctr;    // zero-init at load; reset by last block

__device__ __forceinline__ float warp_sum(float v) {
    #pragma unroll
    for (int off = 16; off > 0; off >>= 1)
        v += __shfl_down_sync(0xFFFFFFFFu, v, off);
    return v;
}

__device__ __forceinline__ float sqdiff4(float4 a, float4 b, float acc) {
    float d;
    d = a.x - b.x; acc = fmaf(d, d, acc);
    d = a.y - b.y; acc = fmaf(d, d, acc);
    d = a.z - b.z; acc = fmaf(d, d, acc);
    d = a.w - b.w; acc = fmaf(d, d, acc);
    return acc;
}

// 4 blocks/SM reg budget (measured sweet spot); 512 CTAs all co-resident.
__global__ void __launch_bounds__(THREADS, 4) fused_loss_kernel(
    const float4* __restrict__ pred4,
    const float4* __restrict__ gt4,
    const float*  __restrict__ pred,   // scalar view for gathers
    const float*  __restrict__ kp,     // (B, N, 2) -> [x, y]
    float* __restrict__ out)
{
    const int lane = threadIdx.x & 31;
    const int gw   = blockIdx.x * (THREADS / 32) + (threadIdx.x >> 5);  // global warp id

    // ---- streaming MSE: exactly 7 warp-contiguous 3KB chunks per warp ----
    float acc[UNROLL];
    #pragma unroll
    for (int u = 0; u < UNROLL; u++) acc[u] = 0.0f;

    #pragma unroll 1
    for (int k = 0; k < CHUNKS_PER_WARP; k++) {
        const int c = gw + k * TOTAL_WARPS;       // interleaved chunk assignment
        const float4* pa = pred4 + c * CHUNK + lane;
        const float4* pb = gt4   + c * CHUNK + lane;
        float4 a[UNROLL], b[UNROLL];
        #pragma unroll
        for (int u = 0; u < UNROLL; u++) a[u] = pa[u * 32];
        #pragma unroll
        for (int u = 0; u < UNROLL; u++) b[u] = pb[u * 32];
        #pragma unroll
        for (int u = 0; u < UNROLL; u++) acc[u] = sqdiff4(a[u], b[u], acc[u]);
    }
    float mse_acc = ((acc[0] + acc[1]) + (acc[2] + acc[3])) + (acc[4] + acc[5]);

    // ---- keypoint gather (first NKP threads) ----
    const int tid_global = blockIdx.x * THREADS + threadIdx.x;
    float pck_acc = 0.0f;
    if (tid_global < NKP) {
        float2 xy = *(const float2*)&kp[2 * tid_global];
        int x = (int)fminf(fmaxf(xy.x, 0.0f), (float)(WW - 1));
        int y = (int)fminf(fmaxf(xy.y, 0.0f), (float)(HH - 1));
        float v = pred[(tid_global * HH + y) * WW + x];
        float e = 1.0f - v;
        pck_acc = e * e;
    }

    // ---- block reduction of both accumulators ----
    __shared__ float s1[THREADS / 32];
    __shared__ float s2[THREADS / 32];
    int wid = threadIdx.x >> 5;
    float m = warp_sum(mse_acc);
    float p = warp_sum(pck_acc);
    if (lane == 0) { s1[wid] = m; s2[wid] = p; }
    __syncthreads();

    __shared__ bool s_is_last;
    if (wid == 0) {
        float mm = (lane < THREADS / 32) ? s1[lane] : 0.0f;
        float pp = (lane < THREADS / 32) ? s2[lane] : 0.0f;
        mm = warp_sum(mm);
        pp = warp_sum(pp);
        if (lane == 0) {
            g_part[blockIdx.x] = make_float2(mm, pp);
            __threadfence();
            unsigned int prev = atomicAdd(&g_done_ctr, 1u);
            s_is_last = (prev == (unsigned int)(gridDim.x - 1));
        }
    }
    __syncthreads();

    // ---- last block finalizes ----
    if (s_is_last) {
        float ma = 0.0f, pa = 0.0f;
        for (int j = threadIdx.x; j < GRID; j += THREADS) {
            float2 v = g_part[j];
            ma += v.x;
            pa += v.y;
        }
        float mw = warp_sum(ma);
        float pw = warp_sum(pa);
        if (lane == 0) { s1[wid] = mw; s2[wid] = pw; }
        __syncthreads();
        if (wid == 0) {
            float mm = (lane < THREADS / 32) ? s1[lane] : 0.0f;
            float pp = (lane < THREADS / 32) ? s2[lane] : 0.0f;
            mm = warp_sum(mm);
            pp = warp_sum(pp);
            if (lane == 0) {
                float mse = mm / (float)((long long)BB * NN * HH * WW);
                float pck = pp / (float)NKP;
                out[0] = mse + pck;   // total (weights are 1.0)
                out[1] = mse;
                out[2] = pck;
                g_done_ctr = 0;       // reset for next graph replay
            }
        }
    }
}

extern "C" void kernel_launch(void* const* d_in, const int* in_sizes, int n_in,
                              void* d_out, int out_size)
{
    const float* pred = (const float*)d_in[0];
    const float* gt   = (const float*)d_in[1];
    const float* kp   = (const float*)d_in[2];
    float* out = (float*)d_out;

    fused_loss_kernel<<<GRID, THREADS>>>(
        (const float4*)pred, (const float4*)gt, pred, kp, out);
}